// round 15
// baseline (speedup 1.0000x reference)
#include <cuda_runtime.h>
#include <cuda_bf16.h>
#include <cuda_fp16.h>
#include <math.h>
#include <cstdint>

// Problem constants (HGCF_3221225472207)
constexpr int NN = 50000;   // nodes
constexpr int CC = 64;      // classes
constexpr int GG = 3;       // metapath graphs
constexpr int EE = 1200000; // edges per graph
constexpr int DD = 256;     // input feat dim
constexpr int HH = 256;     // hidden dim
constexpr int NBLK = 49;    // ceil(NN/1024) scan blocks per graph

// ---------------- device scratch (static, no allocation) ----------------
__device__ int   d_rowptr[GG * (NN + 1)];
__device__ int   d_cursor[GG * NN];
__device__ int   d_bsum[GG * 64];
__device__ __align__(16) int2  d_e0[(size_t)GG * EE];  // {src, exp(e_l0)} by dst
__device__ __align__(16) int2  d_e1[(size_t)GG * EE];  // {src, exp(e_l1)} by dst
__device__ __align__(16) __half d_l16[(size_t)NN * CC];      // label_init fp16
__device__ __align__(16) __half d_h16[(size_t)GG * NN * CC]; // layer0 out fp16
__device__ __align__(16) float  d_h2[(size_t)GG * NN * CC];  // layer1 out fp32
__device__ float d_lp_fb[(size_t)NN * CC];
__device__ float d_ns_fb[(size_t)NN * CC];
// bf16 split operands
__device__ __align__(16) __nv_bfloat16 d_Ahi[(size_t)NN * DD];
__device__ __align__(16) __nv_bfloat16 d_Alo[(size_t)NN * DD];
__device__ __align__(16) __nv_bfloat16 d_W1Thi[HH * DD];   // [n, k] = W1^T
__device__ __align__(16) __nv_bfloat16 d_W1Tlo[HH * DD];
__device__ __align__(16) __nv_bfloat16 d_HMhi[(size_t)NN * HH];
__device__ __align__(16) __nv_bfloat16 d_HMlo[(size_t)NN * HH];
__device__ __align__(16) __nv_bfloat16 d_W2Thi[CC * HH];   // [n, k] = W2^T
__device__ __align__(16) __nv_bfloat16 d_W2Tlo[CC * HH];

// ---------------- warp MMA / async-copy helpers ----------------
__device__ __forceinline__ uint32_t smem_u32(const void* p) {
    uint32_t a;
    asm("{ .reg .u64 t; cvta.to.shared.u64 t, %1; cvt.u32.u64 %0, t; }" : "=r"(a) : "l"(p));
    return a;
}
__device__ __forceinline__ void ldsm_x4(uint32_t (&r)[4], uint32_t addr) {
    asm volatile("ldmatrix.sync.aligned.m8n8.x4.shared.b16 {%0,%1,%2,%3}, [%4];"
                 : "=r"(r[0]), "=r"(r[1]), "=r"(r[2]), "=r"(r[3]) : "r"(addr));
}
__device__ __forceinline__ void mma_bf16(float* c, const uint32_t (&a)[4],
                                         uint32_t b0, uint32_t b1) {
    asm volatile(
        "mma.sync.aligned.m16n8k16.row.col.f32.bf16.bf16.f32 "
        "{%0,%1,%2,%3}, {%4,%5,%6,%7}, {%8,%9}, {%0,%1,%2,%3};"
        : "+f"(c[0]), "+f"(c[1]), "+f"(c[2]), "+f"(c[3])
        : "r"(a[0]), "r"(a[1]), "r"(a[2]), "r"(a[3]), "r"(b0), "r"(b1));
}
__device__ __forceinline__ void cp16(uint32_t dst, const void* src, bool pred) {
    int sz = pred ? 16 : 0;
    asm volatile("cp.async.cg.shared.global [%0], [%1], 16, %2;"
                 :: "r"(dst), "l"(src), "r"(sz));
}
#define CP_COMMIT asm volatile("cp.async.commit_group;" ::: "memory")
#define CP_WAIT1  asm volatile("cp.async.wait_group 1;" ::: "memory")
#define CP_WAIT0  asm volatile("cp.async.wait_group 0;" ::: "memory")

// ---------------- bf16 split conversion kernels ----------------
__global__ void convA_kernel(const float* __restrict__ x,
                             __nv_bfloat16* __restrict__ hi,
                             __nv_bfloat16* __restrict__ lo, int n4) {
    int i = blockIdx.x * blockDim.x + threadIdx.x;
    if (i >= n4) return;
    float4 v = ((const float4*)x)[i];
    __nv_bfloat16 h[4], l[4];
    float vv[4] = {v.x, v.y, v.z, v.w};
    #pragma unroll
    for (int j = 0; j < 4; j++) {
        h[j] = __float2bfloat16(vv[j]);
        l[j] = __float2bfloat16(vv[j] - __bfloat162float(h[j]));
    }
    ((uint2*)hi)[i] = *(uint2*)h;
    ((uint2*)lo)[i] = *(uint2*)l;
}

// transpose + split: out[n*K + k] = in[k*Nc + n]
__global__ void convWT_kernel(const float* __restrict__ in,
                              __nv_bfloat16* __restrict__ hi,
                              __nv_bfloat16* __restrict__ lo, int K, int Nc) {
    int i = blockIdx.x * blockDim.x + threadIdx.x;
    if (i >= K * Nc) return;
    int n = i / K, k = i - n * K;
    float v = in[(size_t)k * Nc + n];
    __nv_bfloat16 h = __float2bfloat16(v);
    hi[i] = h;
    lo[i] = __float2bfloat16(v - __bfloat162float(h));
}

// float -> fp16 (label_init)
__global__ void convL16_kernel(const float* __restrict__ x, int n2) {
    int i = blockIdx.x * blockDim.x + threadIdx.x;
    if (i >= n2) return;
    float2 v = ((const float2*)x)[i];
    ((__half2*)d_l16)[i] = __floats2half2_rn(v.x, v.y);
}

// ---------------- HMMA split GEMM with cp.async double buffering --------
// C[M, Ntile] = Ahi*Bhi + Alo*Bhi + Ahi*Blo, K=256, fp32 accum.
// MODE 0: relu(C+bias) -> bf16 hi/lo split (GEMM1).
// MODE 1: write C+bias as fp32 to nsOut (GEMM2, ns only).
template <int BM, int BN, int MODE>
__global__ void __launch_bounds__(256, 3) hmma_gemm_kernel(
    const __nv_bfloat16* __restrict__ Ahi, const __nv_bfloat16* __restrict__ Alo,
    const __nv_bfloat16* __restrict__ Bhi, const __nv_bfloat16* __restrict__ Blo,
    int M, const float* __restrict__ bias,
    __nv_bfloat16* __restrict__ outHi, __nv_bfloat16* __restrict__ outLo,
    float* __restrict__ nsOut) {
    constexpr int STRIDE = 40;
    constexpr int ASTAGE = BM * STRIDE;
    constexpr int BSTAGE = BN * STRIDE;
    constexpr int BOFF = 4 * ASTAGE;
    constexpr int WARPS_N = (BN == 128) ? 4 : 2;
    constexpr int WARPS_M = 8 / WARPS_N;
    constexpr int WM = BM / WARPS_M;
    constexpr int MF = WM / 16;
    constexpr int NP = 2;

    extern __shared__ __nv_bfloat16 smem[];
    uint32_t sbase = smem_u32(smem);

    int tid = threadIdx.x;
    int wid = tid >> 5, lane = tid & 31;
    int bm = blockIdx.x * BM;
    int bn = blockIdx.y * BN;
    int wm0 = (wid / WARPS_N) * WM;
    int wn0 = (wid % WARPS_N) * 32;

    float acc[MF][2 * NP][4];
    #pragma unroll
    for (int i = 0; i < MF; i++)
        #pragma unroll
        for (int j = 0; j < 2 * NP; j++)
            #pragma unroll
            for (int q = 0; q < 4; q++) acc[i][j][q] = 0.f;

    int a_row = tid >> 2, a_ch = tid & 3;

    auto issue_stage = [&](int kt, int st) {
        int k0 = kt * 32;
        #pragma unroll
        for (int j = 0; j < BM / 64; j++) {
            int row = a_row + j * 64;
            int gm = bm + row;
            bool p = gm < M;
            uint32_t off = (uint32_t)(st * 2 * ASTAGE + row * STRIDE + a_ch * 8) * 2;
            cp16(sbase + off, Ahi + (size_t)gm * 256 + k0 + a_ch * 8, p);
            cp16(sbase + off + ASTAGE * 2, Alo + (size_t)gm * 256 + k0 + a_ch * 8, p);
        }
        #pragma unroll
        for (int j = 0; j < BN / 64; j++) {
            int row = a_row + j * 64;
            uint32_t off = (uint32_t)(BOFF + st * 2 * BSTAGE + row * STRIDE + a_ch * 8) * 2;
            cp16(sbase + off, Bhi + (size_t)(bn + row) * 256 + k0 + a_ch * 8, true);
            cp16(sbase + off + BSTAGE * 2, Blo + (size_t)(bn + row) * 256 + k0 + a_ch * 8, true);
        }
        CP_COMMIT;
    };

    int lrow = lane & 15, lch = lane >> 4;

    issue_stage(0, 0);
    for (int kt = 0; kt < 8; kt++) {
        int st = kt & 1;
        if (kt < 7) { issue_stage(kt + 1, st ^ 1); CP_WAIT1; }
        else        { CP_WAIT0; }
        __syncthreads();

        #pragma unroll
        for (int ks = 0; ks < 2; ks++) {
            uint32_t ah[MF][4], al[MF][4], bh[NP][4], bl[NP][4];
            #pragma unroll
            for (int mf = 0; mf < MF; mf++) {
                uint32_t off = sbase + (uint32_t)(st * 2 * ASTAGE +
                    (wm0 + mf * 16 + lrow) * STRIDE + (ks * 2 + lch) * 8) * 2;
                ldsm_x4(ah[mf], off);
                ldsm_x4(al[mf], off + ASTAGE * 2);
            }
            #pragma unroll
            for (int np = 0; np < NP; np++) {
                uint32_t off = sbase + (uint32_t)(BOFF + st * 2 * BSTAGE +
                    (wn0 + np * 16 + lrow) * STRIDE + (ks * 2 + lch) * 8) * 2;
                ldsm_x4(bh[np], off);
                ldsm_x4(bl[np], off + BSTAGE * 2);
            }
            #pragma unroll
            for (int mf = 0; mf < MF; mf++)
                #pragma unroll
                for (int np = 0; np < NP; np++) {
                    mma_bf16(acc[mf][2 * np + 0], ah[mf], bh[np][0], bh[np][2]);
                    mma_bf16(acc[mf][2 * np + 1], ah[mf], bh[np][1], bh[np][3]);
                    mma_bf16(acc[mf][2 * np + 0], al[mf], bh[np][0], bh[np][2]);
                    mma_bf16(acc[mf][2 * np + 1], al[mf], bh[np][1], bh[np][3]);
                    mma_bf16(acc[mf][2 * np + 0], ah[mf], bl[np][0], bl[np][2]);
                    mma_bf16(acc[mf][2 * np + 1], ah[mf], bl[np][1], bl[np][3]);
                }
        }
        __syncthreads();
    }

    int mrow = lane >> 2, npair = lane & 3;
    #pragma unroll
    for (int mf = 0; mf < MF; mf++) {
        #pragma unroll
        for (int half = 0; half < 2; half++) {
            int gm = bm + wm0 + mf * 16 + mrow + half * 8;
            if (gm >= M) continue;
            #pragma unroll
            for (int nf = 0; nf < 2 * NP; nf++) {
                int gn = bn + wn0 + nf * 8 + 2 * npair;
                float v0 = acc[mf][nf][half * 2 + 0] + bias[gn];
                float v1 = acc[mf][nf][half * 2 + 1] + bias[gn + 1];
                if (MODE == 0) {
                    v0 = fmaxf(v0, 0.f);
                    v1 = fmaxf(v1, 0.f);
                    __nv_bfloat16 h0 = __float2bfloat16(v0);
                    __nv_bfloat16 h1 = __float2bfloat16(v1);
                    __nv_bfloat16 l0 = __float2bfloat16(v0 - __bfloat162float(h0));
                    __nv_bfloat16 l1 = __float2bfloat16(v1 - __bfloat162float(h1));
                    size_t base = (size_t)gm * 256 + gn;
                    __nv_bfloat162 hp; hp.x = h0; hp.y = h1;
                    __nv_bfloat162 lo2; lo2.x = l0; lo2.y = l1;
                    *(__nv_bfloat162*)(outHi + base) = hp;
                    *(__nv_bfloat162*)(outLo + base) = lo2;
                } else {
                    size_t base = (size_t)gm * 64 + gn;
                    float2 nsv; nsv.x = v0; nsv.y = v1;
                    *(float2*)(nsOut + base) = nsv;
                }
            }
        }
    }
}

// ---------------- final combine (tail after join) -----------------------
__global__ void combine_kernel(const float* __restrict__ attention,
                               const float* __restrict__ alpha,
                               const float* __restrict__ h2_0,
                               const float* __restrict__ h2_1,
                               const float* __restrict__ h2_2,
                               const float* __restrict__ ns,
                               float* __restrict__ lp,
                               float* __restrict__ outF) {
    int i = blockIdx.x * blockDim.x + threadIdx.x;   // float4 index
    if (i >= NN * CC / 4) return;
    int node = i >> 4;                               // 16 float4 per node
    float a0 = attention[node * 3 + 0];
    float a1 = attention[node * 3 + 1];
    float a2 = attention[node * 3 + 2];
    float mx = fmaxf(a0, fmaxf(a1, a2));
    float e0 = expf(a0 - mx), e1 = expf(a1 - mx), e2 = expf(a2 - mx);
    float den = e0 + e1 + e2;
    float att0 = e0 / den, att1 = e1 / den, att2 = e2 / den;
    float sg = 1.f / (1.f + expf(-alpha[node]));

    float4 o0 = ((const float4*)h2_0)[i];
    float4 o1 = ((const float4*)h2_1)[i];
    float4 o2 = ((const float4*)h2_2)[i];
    float4 nv = ((const float4*)ns)[i];
    float4 lpv, ov;
    lpv.x = att0 * o0.x + att1 * o1.x + att2 * o2.x;
    lpv.y = att0 * o0.y + att1 * o1.y + att2 * o2.y;
    lpv.z = att0 * o0.z + att1 * o1.z + att2 * o2.z;
    lpv.w = att0 * o0.w + att1 * o1.w + att2 * o2.w;
    ov.x = sg * lpv.x + (1.f - sg) * nv.x;
    ov.y = sg * lpv.y + (1.f - sg) * nv.y;
    ov.z = sg * lpv.z + (1.f - sg) * nv.z;
    ov.w = sg * lpv.w + (1.f - sg) * nv.w;
    ((float4*)lp)[i]   = lpv;
    ((float4*)outF)[i] = ov;
}

// ---------------- CSR build ----------------
__global__ void zero_deg_kernel() {
    int i = blockIdx.x * blockDim.x + threadIdx.x;
    if (i < GG * NN) d_cursor[i] = 0;
}

__global__ void hist_kernel(const int* __restrict__ dst) {
    int i = blockIdx.x * blockDim.x + threadIdx.x;
    if (i >= GG * EE) return;
    int g = i / EE;
    atomicAdd(&d_cursor[g * NN + dst[i]], 1);
}

__global__ void scan1_kernel() {
    int g = blockIdx.y;
    int tid = threadIdx.x;
    int i = blockIdx.x * 1024 + tid;
    int v = (i < NN) ? d_cursor[g * NN + i] : 0;
    unsigned lane = tid & 31, w = tid >> 5;
    int x = v;
    #pragma unroll
    for (int o = 1; o < 32; o <<= 1) {
        int t = __shfl_up_sync(0xffffffffu, x, o);
        if (lane >= o) x += t;
    }
    __shared__ int wsum[32];
    if (lane == 31) wsum[w] = x;
    __syncthreads();
    if (w == 0) {
        int y = wsum[lane];
        #pragma unroll
        for (int o = 1; o < 32; o <<= 1) {
            int t = __shfl_up_sync(0xffffffffu, y, o);
            if (lane >= o) y += t;
        }
        wsum[lane] = y;
    }
    __syncthreads();
    int incl = x + (w > 0 ? wsum[w - 1] : 0);
    int excl = incl - v;
    if (i < NN) d_rowptr[g * (NN + 1) + i] = excl;
    if (tid == 1023) d_bsum[g * 64 + blockIdx.x] = incl;
}

__global__ void scan2_kernel() {
    int g = threadIdx.x;
    if (g >= GG) return;
    int off = 0;
    for (int b = 0; b < NBLK; b++) {
        int t = d_bsum[g * 64 + b];
        d_bsum[g * 64 + b] = off;
        off += t;
    }
    d_rowptr[g * (NN + 1) + NN] = off;
}

__global__ void scan3_kernel() {
    int i = blockIdx.x * blockDim.x + threadIdx.x;
    if (i >= GG * NN) return;
    int g = i / NN, n = i - g * NN;
    int val = d_rowptr[g * (NN + 1) + n] + d_bsum[g * 64 + (n >> 10)];
    d_rowptr[g * (NN + 1) + n] = val;
    d_cursor[g * NN + n] = val;
}

__global__ void scatter_kernel(const int* __restrict__ src,
                               const int* __restrict__ dst,
                               const float* __restrict__ e_edges) {
    int i = blockIdx.x * blockDim.x + threadIdx.x;
    if (i >= GG * EE) return;
    int g = i / EE;
    int v = dst[i];
    int p = atomicAdd(&d_cursor[g * NN + v], 1);
    float e0 = expf(e_edges[i]);
    float e1 = expf(e_edges[(size_t)GG * EE + i]);
    size_t idx = (size_t)g * EE + p;
    int s = src[i];
    d_e0[idx] = make_int2(s, __float_as_int(e0));
    d_e1[idx] = make_int2(s, __float_as_int(e1));
}

// ---------------- propagation: one warp per (graph, dst node) ----------
// (R5 two-loop form: lane-strided denominator loop doubles as an
//  L1 prefetch of the node's 8B/edge record list for the main loop)
__global__ void prop_l0_kernel(const float* __restrict__ train_mask,
                               const float* __restrict__ labels_oh) {
    int w = (blockIdx.x * blockDim.x + threadIdx.x) >> 5;
    int lane = threadIdx.x & 31;
    if (w >= GG * NN) return;
    int g = w / NN, node = w - g * NN;
    const int2* edges = d_e0 + (size_t)g * EE;
    const int* rp = d_rowptr + g * (NN + 1);
    int beg = rp[node], end = rp[node + 1];

    float s = 0.f;
    for (int j = beg + lane; j < end; j += 32) s += __int_as_float(edges[j].y);
    #pragma unroll
    for (int o = 16; o; o >>= 1) s += __shfl_xor_sync(0xffffffffu, s, o);
    float inv = (end > beg) ? 1.f / s : 0.f;

    const __half2* lbl = (const __half2*)d_l16;
    float2 acc = make_float2(0.f, 0.f);
    #pragma unroll 4
    for (int j = beg; j < end; j++) {
        int2 e = edges[j];
        float wt = __int_as_float(e.y) * inv;
        float2 v = __half22float2(lbl[(size_t)e.x * 32 + lane]);
        acc.x = fmaf(v.x, wt, acc.x);
        acc.y = fmaf(v.y, wt, acc.y);
    }
    float tm = train_mask[node];
    float ml = 1.f - tm;
    float2 oh = *(const float2*)(labels_oh + (size_t)node * CC + 2 * lane);
    float2 o;
    o.x = acc.x * ml + oh.x * tm;
    o.y = acc.y * ml + oh.y * tm;
    ((__half2*)d_h16)[(size_t)g * NN * 32 + (size_t)node * 32 + lane] =
        __floats2half2_rn(o.x, o.y);
}

__global__ void prop_l1_kernel(const float* __restrict__ train_mask,
                               const float* __restrict__ labels_oh) {
    int w = (blockIdx.x * blockDim.x + threadIdx.x) >> 5;
    int lane = threadIdx.x & 31;
    if (w >= GG * NN) return;
    int g = w / NN, node = w - g * NN;
    const int2* edges = d_e1 + (size_t)g * EE;
    const int* rp = d_rowptr + g * (NN + 1);
    int beg = rp[node], end = rp[node + 1];

    float s = 0.f;
    for (int j = beg + lane; j < end; j += 32) s += __int_as_float(edges[j].y);
    #pragma unroll
    for (int o = 16; o; o >>= 1) s += __shfl_xor_sync(0xffffffffu, s, o);
    float inv = (end > beg) ? 1.f / s : 0.f;

    const __half2* hg = (const __half2*)d_h16 + (size_t)g * NN * 32;
    float2 acc = make_float2(0.f, 0.f);
    #pragma unroll 4
    for (int j = beg; j < end; j++) {
        int2 e = edges[j];
        float wt = __int_as_float(e.y) * inv;
        float2 v = __half22float2(hg[(size_t)e.x * 32 + lane]);
        acc.x = fmaf(v.x, wt, acc.x);
        acc.y = fmaf(v.y, wt, acc.y);
    }
    float tm = train_mask[node];
    float ml = 1.f - tm;
    float2 oh = *(const float2*)(labels_oh + (size_t)node * CC + 2 * lane);
    float2 o;
    o.x = acc.x * ml + oh.x * tm;
    o.y = acc.y * ml + oh.y * tm;
    *(float2*)(d_h2 + (size_t)g * NN * CC + (size_t)node * CC + 2 * lane) = o;
}

// ---------------- launch ----------------
extern "C" void kernel_launch(void* const* d_in, const int* in_sizes, int n_in,
                              void* d_out, int out_size) {
    const float* features0  = (const float*)d_in[0];
    const float* label_init = (const float*)d_in[1];
    const float* labels_oh  = (const float*)d_in[2];
    const float* train_mask = (const float*)d_in[3];
    const int*   src        = (const int*)d_in[4];
    const int*   dst        = (const int*)d_in[5];
    const float* e_edges    = (const float*)d_in[6];
    const float* attention  = (const float*)d_in[7];
    const float* alpha      = (const float*)d_in[8];
    const float* W1         = (const float*)d_in[9];
    const float* b1         = (const float*)d_in[10];
    const float* W2         = (const float*)d_in[11];
    const float* b2         = (const float*)d_in[12];

    float* out = (float*)d_out;
    float* lp;
    float* ns;
    if (out_size >= 3 * NN * CC) {
        lp = out + (size_t)NN * CC;
        ns = out + 2 * (size_t)NN * CC;
    } else {
        void* p;
        cudaGetSymbolAddress(&p, d_lp_fb); lp = (float*)p;
        cudaGetSymbolAddress(&p, d_ns_fb); ns = (float*)p;
    }

    float* h2base; { void* p; cudaGetSymbolAddress(&p, d_h2); h2base = (float*)p; }
    __nv_bfloat16 *Ahi, *Alo, *W1Thi, *W1Tlo, *HMhi, *HMlo, *W2Thi, *W2Tlo;
    { void* p; cudaGetSymbolAddress(&p, d_Ahi);   Ahi   = (__nv_bfloat16*)p; }
    { void* p; cudaGetSymbolAddress(&p, d_Alo);   Alo   = (__nv_bfloat16*)p; }
    { void* p; cudaGetSymbolAddress(&p, d_W1Thi); W1Thi = (__nv_bfloat16*)p; }
    { void* p; cudaGetSymbolAddress(&p, d_W1Tlo); W1Tlo = (__nv_bfloat16*)p; }
    { void* p; cudaGetSymbolAddress(&p, d_HMhi);  HMhi  = (__nv_bfloat16*)p; }
    { void* p; cudaGetSymbolAddress(&p, d_HMlo);  HMlo  = (__nv_bfloat16*)p; }
    { void* p; cudaGetSymbolAddress(&p, d_W2Thi); W2Thi = (__nv_bfloat16*)p; }
    { void* p; cudaGetSymbolAddress(&p, d_W2Tlo); W2Tlo = (__nv_bfloat16*)p; }

    constexpr int SMEM1 = (4 * 64 * 40 + 4 * 128 * 40) * 2;
    constexpr int SMEM2 = (4 * 128 * 40 + 4 * 64 * 40) * 2;
    cudaFuncSetAttribute((const void*)hmma_gemm_kernel<64, 128, 0>,
                         cudaFuncAttributeMaxDynamicSharedMemorySize, SMEM1);
    cudaFuncSetAttribute((const void*)hmma_gemm_kernel<128, 64, 1>,
                         cudaFuncAttributeMaxDynamicSharedMemorySize, SMEM2);

    // ---- fork-join: branch B (MLP path: GEMM1 + ns GEMM) on side stream ----
    cudaStream_t sB = 0;
    cudaEvent_t evFork = 0, evJoin = 0;
    bool forked = (cudaStreamCreateWithFlags(&sB, cudaStreamNonBlocking) == cudaSuccess) &&
                  (cudaEventCreateWithFlags(&evFork, cudaEventDisableTiming) == cudaSuccess) &&
                  (cudaEventCreateWithFlags(&evJoin, cudaEventDisableTiming) == cudaSuccess);
    cudaStream_t b = forked ? sB : (cudaStream_t)0;

    if (forked) {
        cudaEventRecord(evFork, 0);          // fork point on capture-origin stream
        cudaStreamWaitEvent(sB, evFork, 0);  // sB joins the capture graph
    }

    // ---- branch B: conversions + GEMM1 + ns GEMM (all tensor-pipe work) ----
    convA_kernel<<<(NN * DD / 4 + 255) / 256, 256, 0, b>>>(features0, Ahi, Alo, NN * DD / 4);
    convWT_kernel<<<(DD * HH + 255) / 256, 256, 0, b>>>(W1, W1Thi, W1Tlo, DD, HH);
    convWT_kernel<<<(HH * CC + 255) / 256, 256, 0, b>>>(W2, W2Thi, W2Tlo, HH, CC);
    {
        dim3 grid((NN + 63) / 64, HH / 128);
        hmma_gemm_kernel<64, 128, 0><<<grid, 256, SMEM1, b>>>(
            Ahi, Alo, W1Thi, W1Tlo, NN, b1, HMhi, HMlo, nullptr);
    }
    {
        dim3 grid((NN + 127) / 128, 1);
        hmma_gemm_kernel<128, 64, 1><<<grid, 256, SMEM2, b>>>(
            HMhi, HMlo, W2Thi, W2Tlo, NN, b2, nullptr, nullptr, ns);
    }

    // ---- branch A (origin stream): CSR build + label propagation ----
    convL16_kernel<<<(NN * CC / 2 + 255) / 256, 256>>>(label_init, NN * CC / 2);
    zero_deg_kernel<<<(GG * NN + 255) / 256, 256>>>();
    hist_kernel<<<(GG * EE + 255) / 256, 256>>>(dst);
    { dim3 g1(NBLK, GG); scan1_kernel<<<g1, 1024>>>(); }
    scan2_kernel<<<1, 32>>>();
    scan3_kernel<<<(GG * NN + 255) / 256, 256>>>();
    scatter_kernel<<<(GG * EE + 255) / 256, 256>>>(src, dst, e_edges);

    int pblocks = (GG * NN * 32 + 255) / 256;
    prop_l0_kernel<<<pblocks, 256>>>(train_mask, labels_oh);
    prop_l1_kernel<<<pblocks, 256>>>(train_mask, labels_oh);

    // ---- join: combine needs ns (branch B) and h2 (branch A) ----
    if (forked) {
        cudaEventRecord(evJoin, sB);
        cudaStreamWaitEvent(0, evJoin, 0);
    }
    combine_kernel<<<(NN * CC / 4 + 255) / 256, 256>>>(
        attention, alpha,
        h2base, h2base + (size_t)NN * CC, h2base + 2 * (size_t)NN * CC,
        ns, lp, out);

    if (forked) {
        cudaEventDestroy(evFork);
        cudaEventDestroy(evJoin);
        cudaStreamDestroy(sB);
    } else {
        if (evFork) cudaEventDestroy(evFork);
        if (evJoin) cudaEventDestroy(evJoin);
        if (sB) cudaStreamDestroy(sB);
    }
}

// round 16
// speedup vs baseline: 1.0343x; 1.0343x over previous
#include <cuda_runtime.h>
#include <cuda_bf16.h>
#include <cuda_fp16.h>
#include <math.h>
#include <cstdint>

// Problem constants (HGCF_3221225472207)
constexpr int NN = 50000;   // nodes
constexpr int CC = 64;      // classes
constexpr int GG = 3;       // metapath graphs
constexpr int EE = 1200000; // edges per graph
constexpr int DD = 256;     // input feat dim
constexpr int HH = 256;     // hidden dim
constexpr int NBLK = 49;    // ceil(NN/1024) scan blocks per graph

// ---------------- device scratch (static, no allocation) ----------------
__device__ int   d_rowptr[GG * (NN + 1)];
__device__ int   d_cursor[GG * NN];
__device__ int   d_bsum[GG * 64];
__device__ __align__(16) int4  d_edges[(size_t)GG * EE];
__device__ __align__(16) __half d_l16[(size_t)NN * CC];      // label_init fp16
__device__ __align__(16) __half d_h16[(size_t)GG * NN * CC]; // layer0 out fp16
__device__ __align__(16) float  d_h2[(size_t)GG * NN * CC];  // layer1 out fp32
__device__ float d_lp_fb[(size_t)NN * CC];
__device__ float d_ns_fb[(size_t)NN * CC];
// bf16 split operands
__device__ __align__(16) __nv_bfloat16 d_Ahi[(size_t)NN * DD];
__device__ __align__(16) __nv_bfloat16 d_Alo[(size_t)NN * DD];
__device__ __align__(16) __nv_bfloat16 d_W1Thi[HH * DD];   // [n, k] = W1^T
__device__ __align__(16) __nv_bfloat16 d_W1Tlo[HH * DD];
__device__ __align__(16) __nv_bfloat16 d_HMhi[(size_t)NN * HH];
__device__ __align__(16) __nv_bfloat16 d_HMlo[(size_t)NN * HH];
__device__ __align__(16) __nv_bfloat16 d_W2Thi[CC * HH];   // [n, k] = W2^T
__device__ __align__(16) __nv_bfloat16 d_W2Tlo[CC * HH];

// ---------------- warp MMA / async-copy helpers ----------------
__device__ __forceinline__ uint32_t smem_u32(const void* p) {
    uint32_t a;
    asm("{ .reg .u64 t; cvta.to.shared.u64 t, %1; cvt.u32.u64 %0, t; }" : "=r"(a) : "l"(p));
    return a;
}
__device__ __forceinline__ void ldsm_x4(uint32_t (&r)[4], uint32_t addr) {
    asm volatile("ldmatrix.sync.aligned.m8n8.x4.shared.b16 {%0,%1,%2,%3}, [%4];"
                 : "=r"(r[0]), "=r"(r[1]), "=r"(r[2]), "=r"(r[3]) : "r"(addr));
}
__device__ __forceinline__ void mma_bf16(float* c, const uint32_t (&a)[4],
                                         uint32_t b0, uint32_t b1) {
    asm volatile(
        "mma.sync.aligned.m16n8k16.row.col.f32.bf16.bf16.f32 "
        "{%0,%1,%2,%3}, {%4,%5,%6,%7}, {%8,%9}, {%0,%1,%2,%3};"
        : "+f"(c[0]), "+f"(c[1]), "+f"(c[2]), "+f"(c[3])
        : "r"(a[0]), "r"(a[1]), "r"(a[2]), "r"(a[3]), "r"(b0), "r"(b1));
}
__device__ __forceinline__ void cp16(uint32_t dst, const void* src, bool pred) {
    int sz = pred ? 16 : 0;
    asm volatile("cp.async.cg.shared.global [%0], [%1], 16, %2;"
                 :: "r"(dst), "l"(src), "r"(sz));
}
#define CP_COMMIT asm volatile("cp.async.commit_group;" ::: "memory")
#define CP_WAIT1  asm volatile("cp.async.wait_group 1;" ::: "memory")
#define CP_WAIT0  asm volatile("cp.async.wait_group 0;" ::: "memory")

// ---------------- bf16 split conversion kernels ----------------
__global__ void convA_kernel(const float* __restrict__ x,
                             __nv_bfloat16* __restrict__ hi,
                             __nv_bfloat16* __restrict__ lo, int n4) {
    int i = blockIdx.x * blockDim.x + threadIdx.x;
    if (i >= n4) return;
    float4 v = ((const float4*)x)[i];
    __nv_bfloat16 h[4], l[4];
    float vv[4] = {v.x, v.y, v.z, v.w};
    #pragma unroll
    for (int j = 0; j < 4; j++) {
        h[j] = __float2bfloat16(vv[j]);
        l[j] = __float2bfloat16(vv[j] - __bfloat162float(h[j]));
    }
    ((uint2*)hi)[i] = *(uint2*)h;
    ((uint2*)lo)[i] = *(uint2*)l;
}

// transpose + split: out[n*K + k] = in[k*Nc + n]
__global__ void convWT_kernel(const float* __restrict__ in,
                              __nv_bfloat16* __restrict__ hi,
                              __nv_bfloat16* __restrict__ lo, int K, int Nc) {
    int i = blockIdx.x * blockDim.x + threadIdx.x;
    if (i >= K * Nc) return;
    int n = i / K, k = i - n * K;
    float v = in[(size_t)k * Nc + n];
    __nv_bfloat16 h = __float2bfloat16(v);
    hi[i] = h;
    lo[i] = __float2bfloat16(v - __bfloat162float(h));
}

// float -> fp16 (label_init)
__global__ void convL16_kernel(const float* __restrict__ x, int n2) {
    int i = blockIdx.x * blockDim.x + threadIdx.x;
    if (i >= n2) return;
    float2 v = ((const float2*)x)[i];
    ((__half2*)d_l16)[i] = __floats2half2_rn(v.x, v.y);
}

// ---------------- HMMA split GEMM with cp.async double buffering --------
// C[M, Ntile] = Ahi*Bhi + Alo*Bhi + Ahi*Blo, K=256, fp32 accum.
// MODE 0: relu(C+bias) -> bf16 hi/lo split (GEMM1).
// MODE 1: write C+bias as fp32 to nsOut (GEMM2, ns only).
template <int BM, int BN, int MODE>
__global__ void __launch_bounds__(256, 3) hmma_gemm_kernel(
    const __nv_bfloat16* __restrict__ Ahi, const __nv_bfloat16* __restrict__ Alo,
    const __nv_bfloat16* __restrict__ Bhi, const __nv_bfloat16* __restrict__ Blo,
    int M, const float* __restrict__ bias,
    __nv_bfloat16* __restrict__ outHi, __nv_bfloat16* __restrict__ outLo,
    float* __restrict__ nsOut) {
    constexpr int STRIDE = 40;
    constexpr int ASTAGE = BM * STRIDE;
    constexpr int BSTAGE = BN * STRIDE;
    constexpr int BOFF = 4 * ASTAGE;
    constexpr int WARPS_N = (BN == 128) ? 4 : 2;
    constexpr int WARPS_M = 8 / WARPS_N;
    constexpr int WM = BM / WARPS_M;
    constexpr int MF = WM / 16;
    constexpr int NP = 2;

    extern __shared__ __nv_bfloat16 smem[];
    uint32_t sbase = smem_u32(smem);

    int tid = threadIdx.x;
    int wid = tid >> 5, lane = tid & 31;
    int bm = blockIdx.x * BM;
    int bn = blockIdx.y * BN;
    int wm0 = (wid / WARPS_N) * WM;
    int wn0 = (wid % WARPS_N) * 32;

    float acc[MF][2 * NP][4];
    #pragma unroll
    for (int i = 0; i < MF; i++)
        #pragma unroll
        for (int j = 0; j < 2 * NP; j++)
            #pragma unroll
            for (int q = 0; q < 4; q++) acc[i][j][q] = 0.f;

    int a_row = tid >> 2, a_ch = tid & 3;

    auto issue_stage = [&](int kt, int st) {
        int k0 = kt * 32;
        #pragma unroll
        for (int j = 0; j < BM / 64; j++) {
            int row = a_row + j * 64;
            int gm = bm + row;
            bool p = gm < M;
            uint32_t off = (uint32_t)(st * 2 * ASTAGE + row * STRIDE + a_ch * 8) * 2;
            cp16(sbase + off, Ahi + (size_t)gm * 256 + k0 + a_ch * 8, p);
            cp16(sbase + off + ASTAGE * 2, Alo + (size_t)gm * 256 + k0 + a_ch * 8, p);
        }
        #pragma unroll
        for (int j = 0; j < BN / 64; j++) {
            int row = a_row + j * 64;
            uint32_t off = (uint32_t)(BOFF + st * 2 * BSTAGE + row * STRIDE + a_ch * 8) * 2;
            cp16(sbase + off, Bhi + (size_t)(bn + row) * 256 + k0 + a_ch * 8, true);
            cp16(sbase + off + BSTAGE * 2, Blo + (size_t)(bn + row) * 256 + k0 + a_ch * 8, true);
        }
        CP_COMMIT;
    };

    int lrow = lane & 15, lch = lane >> 4;

    issue_stage(0, 0);
    for (int kt = 0; kt < 8; kt++) {
        int st = kt & 1;
        if (kt < 7) { issue_stage(kt + 1, st ^ 1); CP_WAIT1; }
        else        { CP_WAIT0; }
        __syncthreads();

        #pragma unroll
        for (int ks = 0; ks < 2; ks++) {
            uint32_t ah[MF][4], al[MF][4], bh[NP][4], bl[NP][4];
            #pragma unroll
            for (int mf = 0; mf < MF; mf++) {
                uint32_t off = sbase + (uint32_t)(st * 2 * ASTAGE +
                    (wm0 + mf * 16 + lrow) * STRIDE + (ks * 2 + lch) * 8) * 2;
                ldsm_x4(ah[mf], off);
                ldsm_x4(al[mf], off + ASTAGE * 2);
            }
            #pragma unroll
            for (int np = 0; np < NP; np++) {
                uint32_t off = sbase + (uint32_t)(BOFF + st * 2 * BSTAGE +
                    (wn0 + np * 16 + lrow) * STRIDE + (ks * 2 + lch) * 8) * 2;
                ldsm_x4(bh[np], off);
                ldsm_x4(bl[np], off + BSTAGE * 2);
            }
            #pragma unroll
            for (int mf = 0; mf < MF; mf++)
                #pragma unroll
                for (int np = 0; np < NP; np++) {
                    mma_bf16(acc[mf][2 * np + 0], ah[mf], bh[np][0], bh[np][2]);
                    mma_bf16(acc[mf][2 * np + 1], ah[mf], bh[np][1], bh[np][3]);
                    mma_bf16(acc[mf][2 * np + 0], al[mf], bh[np][0], bh[np][2]);
                    mma_bf16(acc[mf][2 * np + 1], al[mf], bh[np][1], bh[np][3]);
                    mma_bf16(acc[mf][2 * np + 0], ah[mf], bl[np][0], bl[np][2]);
                    mma_bf16(acc[mf][2 * np + 1], ah[mf], bl[np][1], bl[np][3]);
                }
        }
        __syncthreads();
    }

    int mrow = lane >> 2, npair = lane & 3;
    #pragma unroll
    for (int mf = 0; mf < MF; mf++) {
        #pragma unroll
        for (int half = 0; half < 2; half++) {
            int gm = bm + wm0 + mf * 16 + mrow + half * 8;
            if (gm >= M) continue;
            #pragma unroll
            for (int nf = 0; nf < 2 * NP; nf++) {
                int gn = bn + wn0 + nf * 8 + 2 * npair;
                float v0 = acc[mf][nf][half * 2 + 0] + bias[gn];
                float v1 = acc[mf][nf][half * 2 + 1] + bias[gn + 1];
                if (MODE == 0) {
                    v0 = fmaxf(v0, 0.f);
                    v1 = fmaxf(v1, 0.f);
                    __nv_bfloat16 h0 = __float2bfloat16(v0);
                    __nv_bfloat16 h1 = __float2bfloat16(v1);
                    __nv_bfloat16 l0 = __float2bfloat16(v0 - __bfloat162float(h0));
                    __nv_bfloat16 l1 = __float2bfloat16(v1 - __bfloat162float(h1));
                    size_t base = (size_t)gm * 256 + gn;
                    __nv_bfloat162 hp; hp.x = h0; hp.y = h1;
                    __nv_bfloat162 lo2; lo2.x = l0; lo2.y = l1;
                    *(__nv_bfloat162*)(outHi + base) = hp;
                    *(__nv_bfloat162*)(outLo + base) = lo2;
                } else {
                    size_t base = (size_t)gm * 64 + gn;
                    float2 nsv; nsv.x = v0; nsv.y = v1;
                    *(float2*)(nsOut + base) = nsv;
                }
            }
        }
    }
}

// ---------------- final combine (tail after join) -----------------------
__global__ void combine_kernel(const float* __restrict__ attention,
                               const float* __restrict__ alpha,
                               const float* __restrict__ h2_0,
                               const float* __restrict__ h2_1,
                               const float* __restrict__ h2_2,
                               const float* __restrict__ ns,
                               float* __restrict__ lp,
                               float* __restrict__ outF) {
    int i = blockIdx.x * blockDim.x + threadIdx.x;   // float4 index
    if (i >= NN * CC / 4) return;
    int node = i >> 4;                               // 16 float4 per node
    float a0 = attention[node * 3 + 0];
    float a1 = attention[node * 3 + 1];
    float a2 = attention[node * 3 + 2];
    float mx = fmaxf(a0, fmaxf(a1, a2));
    float e0 = expf(a0 - mx), e1 = expf(a1 - mx), e2 = expf(a2 - mx);
    float den = e0 + e1 + e2;
    float att0 = e0 / den, att1 = e1 / den, att2 = e2 / den;
    float sg = 1.f / (1.f + expf(-alpha[node]));

    float4 o0 = ((const float4*)h2_0)[i];
    float4 o1 = ((const float4*)h2_1)[i];
    float4 o2 = ((const float4*)h2_2)[i];
    float4 nv = ((const float4*)ns)[i];
    float4 lpv, ov;
    lpv.x = att0 * o0.x + att1 * o1.x + att2 * o2.x;
    lpv.y = att0 * o0.y + att1 * o1.y + att2 * o2.y;
    lpv.z = att0 * o0.z + att1 * o1.z + att2 * o2.z;
    lpv.w = att0 * o0.w + att1 * o1.w + att2 * o2.w;
    ov.x = sg * lpv.x + (1.f - sg) * nv.x;
    ov.y = sg * lpv.y + (1.f - sg) * nv.y;
    ov.z = sg * lpv.z + (1.f - sg) * nv.z;
    ov.w = sg * lpv.w + (1.f - sg) * nv.w;
    ((float4*)lp)[i]   = lpv;
    ((float4*)outF)[i] = ov;
}

// ---------------- CSR build ----------------
__global__ void hist_kernel(const int* __restrict__ dst) {
    int i = blockIdx.x * blockDim.x + threadIdx.x;
    if (i >= GG * EE) return;
    int g = i / EE;
    atomicAdd(&d_cursor[g * NN + dst[i]], 1);
}

__global__ void scan1_kernel() {
    int g = blockIdx.y;
    int tid = threadIdx.x;
    int i = blockIdx.x * 1024 + tid;
    int v = (i < NN) ? d_cursor[g * NN + i] : 0;
    unsigned lane = tid & 31, w = tid >> 5;
    int x = v;
    #pragma unroll
    for (int o = 1; o < 32; o <<= 1) {
        int t = __shfl_up_sync(0xffffffffu, x, o);
        if (lane >= o) x += t;
    }
    __shared__ int wsum[32];
    if (lane == 31) wsum[w] = x;
    __syncthreads();
    if (w == 0) {
        int y = wsum[lane];
        #pragma unroll
        for (int o = 1; o < 32; o <<= 1) {
            int t = __shfl_up_sync(0xffffffffu, y, o);
            if (lane >= o) y += t;
        }
        wsum[lane] = y;
    }
    __syncthreads();
    int incl = x + (w > 0 ? wsum[w - 1] : 0);
    int excl = incl - v;
    if (i < NN) d_rowptr[g * (NN + 1) + i] = excl;
    if (tid == 1023) d_bsum[g * 64 + blockIdx.x] = incl;
}

// fused scan2+scan3: each block redundantly prefix-scans the 3x49 block
// sums in shared (hot L2), block 0 also writes the per-graph totals.
__global__ void scan23_kernel() {
    __shared__ int pref[GG * NBLK];
    if (threadIdx.x < GG) {
        int g = threadIdx.x;
        int off = 0;
        for (int b = 0; b < NBLK; b++) {
            pref[g * NBLK + b] = off;
            off += d_bsum[g * 64 + b];
        }
        if (blockIdx.x == 0) d_rowptr[g * (NN + 1) + NN] = off;
    }
    __syncthreads();
    int i = blockIdx.x * blockDim.x + threadIdx.x;
    if (i >= GG * NN) return;
    int g = i / NN, n = i - g * NN;
    int val = d_rowptr[g * (NN + 1) + n] + pref[g * NBLK + (n >> 10)];
    d_rowptr[g * (NN + 1) + n] = val;
    d_cursor[g * NN + n] = val;
}

__global__ void scatter_kernel(const int* __restrict__ src,
                               const int* __restrict__ dst,
                               const float* __restrict__ e_edges) {
    int i = blockIdx.x * blockDim.x + threadIdx.x;
    if (i >= GG * EE) return;
    int g = i / EE;
    int v = dst[i];
    int p = atomicAdd(&d_cursor[g * NN + v], 1);
    float e0 = expf(e_edges[i]);
    float e1 = expf(e_edges[(size_t)GG * EE + i]);
    d_edges[(size_t)g * EE + p] =
        make_int4(src[i], __float_as_int(e0), __float_as_int(e1), 0);
}

// ---------------- propagation: one warp per (graph, dst node) ----------
// (R5 two-loop form: lane-strided denominator loop doubles as an
//  L1 prefetch of the node's edge list for the broadcast main loop)
__global__ void prop_l0_kernel(const float* __restrict__ train_mask,
                               const float* __restrict__ labels_oh) {
    int w = (blockIdx.x * blockDim.x + threadIdx.x) >> 5;
    int lane = threadIdx.x & 31;
    if (w >= GG * NN) return;
    int g = w / NN, node = w - g * NN;
    const int4* edges = d_edges + (size_t)g * EE;
    const int* rp = d_rowptr + g * (NN + 1);
    int beg = rp[node], end = rp[node + 1];

    float s = 0.f;
    for (int j = beg + lane; j < end; j += 32) s += __int_as_float(edges[j].y);
    #pragma unroll
    for (int o = 16; o; o >>= 1) s += __shfl_xor_sync(0xffffffffu, s, o);
    float inv = (end > beg) ? 1.f / s : 0.f;

    const __half2* lbl = (const __half2*)d_l16;
    float2 acc = make_float2(0.f, 0.f);
    #pragma unroll 4
    for (int j = beg; j < end; j++) {
        int4 e = edges[j];
        float wt = __int_as_float(e.y) * inv;
        float2 v = __half22float2(lbl[(size_t)e.x * 32 + lane]);
        acc.x = fmaf(v.x, wt, acc.x);
        acc.y = fmaf(v.y, wt, acc.y);
    }
    float tm = train_mask[node];
    float ml = 1.f - tm;
    float2 oh = *(const float2*)(labels_oh + (size_t)node * CC + 2 * lane);
    float2 o;
    o.x = acc.x * ml + oh.x * tm;
    o.y = acc.y * ml + oh.y * tm;
    ((__half2*)d_h16)[(size_t)g * NN * 32 + (size_t)node * 32 + lane] =
        __floats2half2_rn(o.x, o.y);
}

__global__ void prop_l1_kernel(const float* __restrict__ train_mask,
                               const float* __restrict__ labels_oh) {
    int w = (blockIdx.x * blockDim.x + threadIdx.x) >> 5;
    int lane = threadIdx.x & 31;
    if (w >= GG * NN) return;
    int g = w / NN, node = w - g * NN;
    const int4* edges = d_edges + (size_t)g * EE;
    const int* rp = d_rowptr + g * (NN + 1);
    int beg = rp[node], end = rp[node + 1];

    float s = 0.f;
    for (int j = beg + lane; j < end; j += 32) s += __int_as_float(edges[j].z);
    #pragma unroll
    for (int o = 16; o; o >>= 1) s += __shfl_xor_sync(0xffffffffu, s, o);
    float inv = (end > beg) ? 1.f / s : 0.f;

    const __half2* hg = (const __half2*)d_h16 + (size_t)g * NN * 32;
    float2 acc = make_float2(0.f, 0.f);
    #pragma unroll 4
    for (int j = beg; j < end; j++) {
        int4 e = edges[j];
        float wt = __int_as_float(e.z) * inv;
        float2 v = __half22float2(hg[(size_t)e.x * 32 + lane]);
        acc.x = fmaf(v.x, wt, acc.x);
        acc.y = fmaf(v.y, wt, acc.y);
    }
    float tm = train_mask[node];
    float ml = 1.f - tm;
    float2 oh = *(const float2*)(labels_oh + (size_t)node * CC + 2 * lane);
    float2 o;
    o.x = acc.x * ml + oh.x * tm;
    o.y = acc.y * ml + oh.y * tm;
    *(float2*)(d_h2 + (size_t)g * NN * CC + (size_t)node * CC + 2 * lane) = o;
}

// ---------------- launch ----------------
extern "C" void kernel_launch(void* const* d_in, const int* in_sizes, int n_in,
                              void* d_out, int out_size) {
    const float* features0  = (const float*)d_in[0];
    const float* label_init = (const float*)d_in[1];
    const float* labels_oh  = (const float*)d_in[2];
    const float* train_mask = (const float*)d_in[3];
    const int*   src        = (const int*)d_in[4];
    const int*   dst        = (const int*)d_in[5];
    const float* e_edges    = (const float*)d_in[6];
    const float* attention  = (const float*)d_in[7];
    const float* alpha      = (const float*)d_in[8];
    const float* W1         = (const float*)d_in[9];
    const float* b1         = (const float*)d_in[10];
    const float* W2         = (const float*)d_in[11];
    const float* b2         = (const float*)d_in[12];

    float* out = (float*)d_out;
    float* lp;
    float* ns;
    if (out_size >= 3 * NN * CC) {
        lp = out + (size_t)NN * CC;
        ns = out + 2 * (size_t)NN * CC;
    } else {
        void* p;
        cudaGetSymbolAddress(&p, d_lp_fb); lp = (float*)p;
        cudaGetSymbolAddress(&p, d_ns_fb); ns = (float*)p;
    }

    float* h2base; { void* p; cudaGetSymbolAddress(&p, d_h2); h2base = (float*)p; }
    int* cursor;   { void* p; cudaGetSymbolAddress(&p, d_cursor); cursor = (int*)p; }
    __nv_bfloat16 *Ahi, *Alo, *W1Thi, *W1Tlo, *HMhi, *HMlo, *W2Thi, *W2Tlo;
    { void* p; cudaGetSymbolAddress(&p, d_Ahi);   Ahi   = (__nv_bfloat16*)p; }
    { void* p; cudaGetSymbolAddress(&p, d_Alo);   Alo   = (__nv_bfloat16*)p; }
    { void* p; cudaGetSymbolAddress(&p, d_W1Thi); W1Thi = (__nv_bfloat16*)p; }
    { void* p; cudaGetSymbolAddress(&p, d_W1Tlo); W1Tlo = (__nv_bfloat16*)p; }
    { void* p; cudaGetSymbolAddress(&p, d_HMhi);  HMhi  = (__nv_bfloat16*)p; }
    { void* p; cudaGetSymbolAddress(&p, d_HMlo);  HMlo  = (__nv_bfloat16*)p; }
    { void* p; cudaGetSymbolAddress(&p, d_W2Thi); W2Thi = (__nv_bfloat16*)p; }
    { void* p; cudaGetSymbolAddress(&p, d_W2Tlo); W2Tlo = (__nv_bfloat16*)p; }

    constexpr int SMEM1 = (4 * 64 * 40 + 4 * 128 * 40) * 2;
    constexpr int SMEM2 = (4 * 128 * 40 + 4 * 64 * 40) * 2;
    cudaFuncSetAttribute((const void*)hmma_gemm_kernel<64, 128, 0>,
                         cudaFuncAttributeMaxDynamicSharedMemorySize, SMEM1);
    cudaFuncSetAttribute((const void*)hmma_gemm_kernel<128, 64, 1>,
                         cudaFuncAttributeMaxDynamicSharedMemorySize, SMEM2);

    // ---- fork-join: branch B (MLP path: GEMM1 + ns GEMM) on side stream ----
    cudaStream_t sB = 0;
    cudaEvent_t evFork = 0, evJoin = 0;
    bool forked = (cudaStreamCreateWithFlags(&sB, cudaStreamNonBlocking) == cudaSuccess) &&
                  (cudaEventCreateWithFlags(&evFork, cudaEventDisableTiming) == cudaSuccess) &&
                  (cudaEventCreateWithFlags(&evJoin, cudaEventDisableTiming) == cudaSuccess);
    cudaStream_t b = forked ? sB : (cudaStream_t)0;

    if (forked) {
        cudaEventRecord(evFork, 0);          // fork point on capture-origin stream
        cudaStreamWaitEvent(sB, evFork, 0);  // sB joins the capture graph
    }

    // ---- branch B: conversions + GEMM1 + ns GEMM (all tensor-pipe work) ----
    convA_kernel<<<(NN * DD / 4 + 255) / 256, 256, 0, b>>>(features0, Ahi, Alo, NN * DD / 4);
    convWT_kernel<<<(DD * HH + 255) / 256, 256, 0, b>>>(W1, W1Thi, W1Tlo, DD, HH);
    convWT_kernel<<<(HH * CC + 255) / 256, 256, 0, b>>>(W2, W2Thi, W2Tlo, HH, CC);
    {
        dim3 grid((NN + 63) / 64, HH / 128);
        hmma_gemm_kernel<64, 128, 0><<<grid, 256, SMEM1, b>>>(
            Ahi, Alo, W1Thi, W1Tlo, NN, b1, HMhi, HMlo, nullptr);
    }
    {
        dim3 grid((NN + 127) / 128, 1);
        hmma_gemm_kernel<128, 64, 1><<<grid, 256, SMEM2, b>>>(
            HMhi, HMlo, W2Thi, W2Tlo, NN, b2, nullptr, nullptr, ns);
    }

    // ---- branch A (origin stream): CSR build + label propagation ----
    cudaMemsetAsync(cursor, 0, (size_t)GG * NN * sizeof(int), 0);
    convL16_kernel<<<(NN * CC / 2 + 255) / 256, 256>>>(label_init, NN * CC / 2);
    hist_kernel<<<(GG * EE + 255) / 256, 256>>>(dst);
    { dim3 g1(NBLK, GG); scan1_kernel<<<g1, 1024>>>(); }
    scan23_kernel<<<(GG * NN + 255) / 256, 256>>>();
    scatter_kernel<<<(GG * EE + 255) / 256, 256>>>(src, dst, e_edges);

    int pblocks = (GG * NN * 32 + 255) / 256;
    prop_l0_kernel<<<pblocks, 256>>>(train_mask, labels_oh);
    prop_l1_kernel<<<pblocks, 256>>>(train_mask, labels_oh);

    // ---- join: combine needs ns (branch B) and h2 (branch A) ----
    if (forked) {
        cudaEventRecord(evJoin, sB);
        cudaStreamWaitEvent(0, evJoin, 0);
    }
    combine_kernel<<<(NN * CC / 4 + 255) / 256, 256>>>(
        attention, alpha,
        h2base, h2base + (size_t)NN * CC, h2base + 2 * (size_t)NN * CC,
        ns, lp, out);

    if (forked) {
        cudaEventDestroy(evFork);
        cudaEventDestroy(evJoin);
        cudaStreamDestroy(sB);
    } else {
        if (evFork) cudaEventDestroy(evFork);
        if (evJoin) cudaEventDestroy(evJoin);
        if (sB) cudaStreamDestroy(sB);
    }
}

// round 17
// speedup vs baseline: 1.0452x; 1.0106x over previous
#include <cuda_runtime.h>
#include <cuda_bf16.h>
#include <cuda_fp16.h>
#include <math.h>
#include <cstdint>

// Problem constants (HGCF_3221225472207)
constexpr int NN = 50000;   // nodes
constexpr int CC = 64;      // classes
constexpr int GG = 3;       // metapath graphs
constexpr int EE = 1200000; // edges per graph
constexpr int DD = 256;     // input feat dim
constexpr int HH = 256;     // hidden dim
constexpr int NBLK = 49;    // ceil(NN/1024) scan blocks per graph

// ---------------- device scratch (static, no allocation) ----------------
__device__ int   d_rowptr[GG * (NN + 1)];
__device__ int   d_cursor[GG * NN];
__device__ int   d_bsum[GG * 64];
__device__ __align__(16) int4  d_edges[(size_t)GG * EE];
__device__ __align__(16) __half d_l16[(size_t)NN * CC];      // label_init fp16
__device__ __align__(16) __half d_h16[(size_t)GG * NN * CC]; // layer0 out fp16
__device__ __align__(16) float  d_h2[(size_t)GG * NN * CC];  // layer1 out fp32
__device__ float d_lp_fb[(size_t)NN * CC];
__device__ float d_ns_fb[(size_t)NN * CC];
// bf16 split operands
__device__ __align__(16) __nv_bfloat16 d_Ahi[(size_t)NN * DD];
__device__ __align__(16) __nv_bfloat16 d_Alo[(size_t)NN * DD];
__device__ __align__(16) __nv_bfloat16 d_W1Thi[HH * DD];   // [n, k] = W1^T
__device__ __align__(16) __nv_bfloat16 d_W1Tlo[HH * DD];
__device__ __align__(16) __nv_bfloat16 d_HMhi[(size_t)NN * HH];
__device__ __align__(16) __nv_bfloat16 d_HMlo[(size_t)NN * HH];
__device__ __align__(16) __nv_bfloat16 d_W2Thi[CC * HH];   // [n, k] = W2^T
__device__ __align__(16) __nv_bfloat16 d_W2Tlo[CC * HH];

// ---------------- warp MMA / async-copy helpers ----------------
__device__ __forceinline__ uint32_t smem_u32(const void* p) {
    uint32_t a;
    asm("{ .reg .u64 t; cvta.to.shared.u64 t, %1; cvt.u32.u64 %0, t; }" : "=r"(a) : "l"(p));
    return a;
}
__device__ __forceinline__ void ldsm_x4(uint32_t (&r)[4], uint32_t addr) {
    asm volatile("ldmatrix.sync.aligned.m8n8.x4.shared.b16 {%0,%1,%2,%3}, [%4];"
                 : "=r"(r[0]), "=r"(r[1]), "=r"(r[2]), "=r"(r[3]) : "r"(addr));
}
__device__ __forceinline__ void mma_bf16(float* c, const uint32_t (&a)[4],
                                         uint32_t b0, uint32_t b1) {
    asm volatile(
        "mma.sync.aligned.m16n8k16.row.col.f32.bf16.bf16.f32 "
        "{%0,%1,%2,%3}, {%4,%5,%6,%7}, {%8,%9}, {%0,%1,%2,%3};"
        : "+f"(c[0]), "+f"(c[1]), "+f"(c[2]), "+f"(c[3])
        : "r"(a[0]), "r"(a[1]), "r"(a[2]), "r"(a[3]), "r"(b0), "r"(b1));
}
__device__ __forceinline__ void cp16(uint32_t dst, const void* src, bool pred) {
    int sz = pred ? 16 : 0;
    asm volatile("cp.async.cg.shared.global [%0], [%1], 16, %2;"
                 :: "r"(dst), "l"(src), "r"(sz));
}
#define CP_COMMIT asm volatile("cp.async.commit_group;" ::: "memory")
#define CP_WAIT1  asm volatile("cp.async.wait_group 1;" ::: "memory")
#define CP_WAIT0  asm volatile("cp.async.wait_group 0;" ::: "memory")

// ---------------- bf16 split conversion kernels ----------------
__global__ void convA_kernel(const float* __restrict__ x,
                             __nv_bfloat16* __restrict__ hi,
                             __nv_bfloat16* __restrict__ lo, int n4) {
    int i = blockIdx.x * blockDim.x + threadIdx.x;
    if (i >= n4) return;
    float4 v = ((const float4*)x)[i];
    __nv_bfloat16 h[4], l[4];
    float vv[4] = {v.x, v.y, v.z, v.w};
    #pragma unroll
    for (int j = 0; j < 4; j++) {
        h[j] = __float2bfloat16(vv[j]);
        l[j] = __float2bfloat16(vv[j] - __bfloat162float(h[j]));
    }
    ((uint2*)hi)[i] = *(uint2*)h;
    ((uint2*)lo)[i] = *(uint2*)l;
}

// transpose + split: out[n*K + k] = in[k*Nc + n]
__global__ void convWT_kernel(const float* __restrict__ in,
                              __nv_bfloat16* __restrict__ hi,
                              __nv_bfloat16* __restrict__ lo, int K, int Nc) {
    int i = blockIdx.x * blockDim.x + threadIdx.x;
    if (i >= K * Nc) return;
    int n = i / K, k = i - n * K;
    float v = in[(size_t)k * Nc + n];
    __nv_bfloat16 h = __float2bfloat16(v);
    hi[i] = h;
    lo[i] = __float2bfloat16(v - __bfloat162float(h));
}

// float -> fp16 (label_init)
__global__ void convL16_kernel(const float* __restrict__ x, int n2) {
    int i = blockIdx.x * blockDim.x + threadIdx.x;
    if (i >= n2) return;
    float2 v = ((const float2*)x)[i];
    ((__half2*)d_l16)[i] = __floats2half2_rn(v.x, v.y);
}

// ---------------- HMMA split GEMM with cp.async double buffering --------
// C[M, Ntile] = Ahi*Bhi + Alo*Bhi + Ahi*Blo, K=256, fp32 accum.
// MODE 0: relu(C+bias) -> bf16 hi/lo split (GEMM1).
// MODE 1: write C+bias as fp32 to nsOut (GEMM2, ns only).
template <int BM, int BN, int MODE>
__global__ void __launch_bounds__(256, 3) hmma_gemm_kernel(
    const __nv_bfloat16* __restrict__ Ahi, const __nv_bfloat16* __restrict__ Alo,
    const __nv_bfloat16* __restrict__ Bhi, const __nv_bfloat16* __restrict__ Blo,
    int M, const float* __restrict__ bias,
    __nv_bfloat16* __restrict__ outHi, __nv_bfloat16* __restrict__ outLo,
    float* __restrict__ nsOut) {
    constexpr int STRIDE = 40;
    constexpr int ASTAGE = BM * STRIDE;
    constexpr int BSTAGE = BN * STRIDE;
    constexpr int BOFF = 4 * ASTAGE;
    constexpr int WARPS_N = (BN == 128) ? 4 : 2;
    constexpr int WARPS_M = 8 / WARPS_N;
    constexpr int WM = BM / WARPS_M;
    constexpr int MF = WM / 16;
    constexpr int NP = 2;

    extern __shared__ __nv_bfloat16 smem[];
    uint32_t sbase = smem_u32(smem);

    int tid = threadIdx.x;
    int wid = tid >> 5, lane = tid & 31;
    int bm = blockIdx.x * BM;
    int bn = blockIdx.y * BN;
    int wm0 = (wid / WARPS_N) * WM;
    int wn0 = (wid % WARPS_N) * 32;

    float acc[MF][2 * NP][4];
    #pragma unroll
    for (int i = 0; i < MF; i++)
        #pragma unroll
        for (int j = 0; j < 2 * NP; j++)
            #pragma unroll
            for (int q = 0; q < 4; q++) acc[i][j][q] = 0.f;

    int a_row = tid >> 2, a_ch = tid & 3;

    auto issue_stage = [&](int kt, int st) {
        int k0 = kt * 32;
        #pragma unroll
        for (int j = 0; j < BM / 64; j++) {
            int row = a_row + j * 64;
            int gm = bm + row;
            bool p = gm < M;
            uint32_t off = (uint32_t)(st * 2 * ASTAGE + row * STRIDE + a_ch * 8) * 2;
            cp16(sbase + off, Ahi + (size_t)gm * 256 + k0 + a_ch * 8, p);
            cp16(sbase + off + ASTAGE * 2, Alo + (size_t)gm * 256 + k0 + a_ch * 8, p);
        }
        #pragma unroll
        for (int j = 0; j < BN / 64; j++) {
            int row = a_row + j * 64;
            uint32_t off = (uint32_t)(BOFF + st * 2 * BSTAGE + row * STRIDE + a_ch * 8) * 2;
            cp16(sbase + off, Bhi + (size_t)(bn + row) * 256 + k0 + a_ch * 8, true);
            cp16(sbase + off + BSTAGE * 2, Blo + (size_t)(bn + row) * 256 + k0 + a_ch * 8, true);
        }
        CP_COMMIT;
    };

    int lrow = lane & 15, lch = lane >> 4;

    issue_stage(0, 0);
    for (int kt = 0; kt < 8; kt++) {
        int st = kt & 1;
        if (kt < 7) { issue_stage(kt + 1, st ^ 1); CP_WAIT1; }
        else        { CP_WAIT0; }
        __syncthreads();

        #pragma unroll
        for (int ks = 0; ks < 2; ks++) {
            uint32_t ah[MF][4], al[MF][4], bh[NP][4], bl[NP][4];
            #pragma unroll
            for (int mf = 0; mf < MF; mf++) {
                uint32_t off = sbase + (uint32_t)(st * 2 * ASTAGE +
                    (wm0 + mf * 16 + lrow) * STRIDE + (ks * 2 + lch) * 8) * 2;
                ldsm_x4(ah[mf], off);
                ldsm_x4(al[mf], off + ASTAGE * 2);
            }
            #pragma unroll
            for (int np = 0; np < NP; np++) {
                uint32_t off = sbase + (uint32_t)(BOFF + st * 2 * BSTAGE +
                    (wn0 + np * 16 + lrow) * STRIDE + (ks * 2 + lch) * 8) * 2;
                ldsm_x4(bh[np], off);
                ldsm_x4(bl[np], off + BSTAGE * 2);
            }
            #pragma unroll
            for (int mf = 0; mf < MF; mf++)
                #pragma unroll
                for (int np = 0; np < NP; np++) {
                    mma_bf16(acc[mf][2 * np + 0], ah[mf], bh[np][0], bh[np][2]);
                    mma_bf16(acc[mf][2 * np + 1], ah[mf], bh[np][1], bh[np][3]);
                    mma_bf16(acc[mf][2 * np + 0], al[mf], bh[np][0], bh[np][2]);
                    mma_bf16(acc[mf][2 * np + 1], al[mf], bh[np][1], bh[np][3]);
                    mma_bf16(acc[mf][2 * np + 0], ah[mf], bl[np][0], bl[np][2]);
                    mma_bf16(acc[mf][2 * np + 1], ah[mf], bl[np][1], bl[np][3]);
                }
        }
        __syncthreads();
    }

    int mrow = lane >> 2, npair = lane & 3;
    #pragma unroll
    for (int mf = 0; mf < MF; mf++) {
        #pragma unroll
        for (int half = 0; half < 2; half++) {
            int gm = bm + wm0 + mf * 16 + mrow + half * 8;
            if (gm >= M) continue;
            #pragma unroll
            for (int nf = 0; nf < 2 * NP; nf++) {
                int gn = bn + wn0 + nf * 8 + 2 * npair;
                float v0 = acc[mf][nf][half * 2 + 0] + bias[gn];
                float v1 = acc[mf][nf][half * 2 + 1] + bias[gn + 1];
                if (MODE == 0) {
                    v0 = fmaxf(v0, 0.f);
                    v1 = fmaxf(v1, 0.f);
                    __nv_bfloat16 h0 = __float2bfloat16(v0);
                    __nv_bfloat16 h1 = __float2bfloat16(v1);
                    __nv_bfloat16 l0 = __float2bfloat16(v0 - __bfloat162float(h0));
                    __nv_bfloat16 l1 = __float2bfloat16(v1 - __bfloat162float(h1));
                    size_t base = (size_t)gm * 256 + gn;
                    __nv_bfloat162 hp; hp.x = h0; hp.y = h1;
                    __nv_bfloat162 lo2; lo2.x = l0; lo2.y = l1;
                    *(__nv_bfloat162*)(outHi + base) = hp;
                    *(__nv_bfloat162*)(outLo + base) = lo2;
                } else {
                    size_t base = (size_t)gm * 64 + gn;
                    float2 nsv; nsv.x = v0; nsv.y = v1;
                    *(float2*)(nsOut + base) = nsv;
                }
            }
        }
    }
}

// ---------------- final combine (tail after join) -----------------------
__global__ void combine_kernel(const float* __restrict__ attention,
                               const float* __restrict__ alpha,
                               const float* __restrict__ h2_0,
                               const float* __restrict__ h2_1,
                               const float* __restrict__ h2_2,
                               const float* __restrict__ ns,
                               float* __restrict__ lp,
                               float* __restrict__ outF) {
    int i = blockIdx.x * blockDim.x + threadIdx.x;   // float4 index
    if (i >= NN * CC / 4) return;
    int node = i >> 4;                               // 16 float4 per node
    float a0 = attention[node * 3 + 0];
    float a1 = attention[node * 3 + 1];
    float a2 = attention[node * 3 + 2];
    float mx = fmaxf(a0, fmaxf(a1, a2));
    float e0 = expf(a0 - mx), e1 = expf(a1 - mx), e2 = expf(a2 - mx);
    float den = e0 + e1 + e2;
    float att0 = e0 / den, att1 = e1 / den, att2 = e2 / den;
    float sg = 1.f / (1.f + expf(-alpha[node]));

    float4 o0 = ((const float4*)h2_0)[i];
    float4 o1 = ((const float4*)h2_1)[i];
    float4 o2 = ((const float4*)h2_2)[i];
    float4 nv = ((const float4*)ns)[i];
    float4 lpv, ov;
    lpv.x = att0 * o0.x + att1 * o1.x + att2 * o2.x;
    lpv.y = att0 * o0.y + att1 * o1.y + att2 * o2.y;
    lpv.z = att0 * o0.z + att1 * o1.z + att2 * o2.z;
    lpv.w = att0 * o0.w + att1 * o1.w + att2 * o2.w;
    ov.x = sg * lpv.x + (1.f - sg) * nv.x;
    ov.y = sg * lpv.y + (1.f - sg) * nv.y;
    ov.z = sg * lpv.z + (1.f - sg) * nv.z;
    ov.w = sg * lpv.w + (1.f - sg) * nv.w;
    ((float4*)lp)[i]   = lpv;
    ((float4*)outF)[i] = ov;
}

// ---------------- CSR build ----------------
__global__ void zero_deg_kernel() {
    int i = blockIdx.x * blockDim.x + threadIdx.x;
    if (i < GG * NN) d_cursor[i] = 0;
}

__global__ void hist_kernel(const int* __restrict__ dst) {
    int i = blockIdx.x * blockDim.x + threadIdx.x;
    if (i >= GG * EE) return;
    int g = i / EE;
    atomicAdd(&d_cursor[g * NN + dst[i]], 1);
}

__global__ void scan1_kernel() {
    int g = blockIdx.y;
    int tid = threadIdx.x;
    int i = blockIdx.x * 1024 + tid;
    int v = (i < NN) ? d_cursor[g * NN + i] : 0;
    unsigned lane = tid & 31, w = tid >> 5;
    int x = v;
    #pragma unroll
    for (int o = 1; o < 32; o <<= 1) {
        int t = __shfl_up_sync(0xffffffffu, x, o);
        if (lane >= o) x += t;
    }
    __shared__ int wsum[32];
    if (lane == 31) wsum[w] = x;
    __syncthreads();
    if (w == 0) {
        int y = wsum[lane];
        #pragma unroll
        for (int o = 1; o < 32; o <<= 1) {
            int t = __shfl_up_sync(0xffffffffu, y, o);
            if (lane >= o) y += t;
        }
        wsum[lane] = y;
    }
    __syncthreads();
    int incl = x + (w > 0 ? wsum[w - 1] : 0);
    int excl = incl - v;
    if (i < NN) d_rowptr[g * (NN + 1) + i] = excl;
    if (tid == 1023) d_bsum[g * 64 + blockIdx.x] = incl;
}

__global__ void scan2_kernel() {
    int g = threadIdx.x;
    if (g >= GG) return;
    int off = 0;
    for (int b = 0; b < NBLK; b++) {
        int t = d_bsum[g * 64 + b];
        d_bsum[g * 64 + b] = off;
        off += t;
    }
    d_rowptr[g * (NN + 1) + NN] = off;
}

__global__ void scan3_kernel() {
    int i = blockIdx.x * blockDim.x + threadIdx.x;
    if (i >= GG * NN) return;
    int g = i / NN, n = i - g * NN;
    int val = d_rowptr[g * (NN + 1) + n] + d_bsum[g * 64 + (n >> 10)];
    d_rowptr[g * (NN + 1) + n] = val;
    d_cursor[g * NN + n] = val;
}

__global__ void scatter_kernel(const int* __restrict__ src,
                               const int* __restrict__ dst,
                               const float* __restrict__ e_edges) {
    int i = blockIdx.x * blockDim.x + threadIdx.x;
    if (i >= GG * EE) return;
    int g = i / EE;
    int v = dst[i];
    int p = atomicAdd(&d_cursor[g * NN + v], 1);
    float e0 = expf(e_edges[i]);
    float e1 = expf(e_edges[(size_t)GG * EE + i]);
    d_edges[(size_t)g * EE + p] =
        make_int4(src[i], __float_as_int(e0), __float_as_int(e1), 0);
}

// ---------------- propagation: one warp per (graph, dst node) ----------
// (R5 two-loop form: lane-strided denominator loop doubles as an
//  L1 prefetch of the node's edge list for the broadcast main loop)
__global__ void prop_l0_kernel(const float* __restrict__ train_mask,
                               const float* __restrict__ labels_oh) {
    int w = (blockIdx.x * blockDim.x + threadIdx.x) >> 5;
    int lane = threadIdx.x & 31;
    if (w >= GG * NN) return;
    int g = w / NN, node = w - g * NN;
    const int4* edges = d_edges + (size_t)g * EE;
    const int* rp = d_rowptr + g * (NN + 1);
    int beg = rp[node], end = rp[node + 1];

    float s = 0.f;
    for (int j = beg + lane; j < end; j += 32) s += __int_as_float(edges[j].y);
    #pragma unroll
    for (int o = 16; o; o >>= 1) s += __shfl_xor_sync(0xffffffffu, s, o);
    float inv = (end > beg) ? 1.f / s : 0.f;

    const __half2* lbl = (const __half2*)d_l16;
    float2 acc = make_float2(0.f, 0.f);
    #pragma unroll 4
    for (int j = beg; j < end; j++) {
        int4 e = edges[j];
        float wt = __int_as_float(e.y) * inv;
        float2 v = __half22float2(lbl[(size_t)e.x * 32 + lane]);
        acc.x = fmaf(v.x, wt, acc.x);
        acc.y = fmaf(v.y, wt, acc.y);
    }
    float tm = train_mask[node];
    float ml = 1.f - tm;
    float2 oh = *(const float2*)(labels_oh + (size_t)node * CC + 2 * lane);
    float2 o;
    o.x = acc.x * ml + oh.x * tm;
    o.y = acc.y * ml + oh.y * tm;
    ((__half2*)d_h16)[(size_t)g * NN * 32 + (size_t)node * 32 + lane] =
        __floats2half2_rn(o.x, o.y);
}

__global__ void prop_l1_kernel(const float* __restrict__ train_mask,
                               const float* __restrict__ labels_oh) {
    int w = (blockIdx.x * blockDim.x + threadIdx.x) >> 5;
    int lane = threadIdx.x & 31;
    if (w >= GG * NN) return;
    int g = w / NN, node = w - g * NN;
    const int4* edges = d_edges + (size_t)g * EE;
    const int* rp = d_rowptr + g * (NN + 1);
    int beg = rp[node], end = rp[node + 1];

    float s = 0.f;
    for (int j = beg + lane; j < end; j += 32) s += __int_as_float(edges[j].z);
    #pragma unroll
    for (int o = 16; o; o >>= 1) s += __shfl_xor_sync(0xffffffffu, s, o);
    float inv = (end > beg) ? 1.f / s : 0.f;

    const __half2* hg = (const __half2*)d_h16 + (size_t)g * NN * 32;
    float2 acc = make_float2(0.f, 0.f);
    #pragma unroll 4
    for (int j = beg; j < end; j++) {
        int4 e = edges[j];
        float wt = __int_as_float(e.z) * inv;
        float2 v = __half22float2(hg[(size_t)e.x * 32 + lane]);
        acc.x = fmaf(v.x, wt, acc.x);
        acc.y = fmaf(v.y, wt, acc.y);
    }
    float tm = train_mask[node];
    float ml = 1.f - tm;
    float2 oh = *(const float2*)(labels_oh + (size_t)node * CC + 2 * lane);
    float2 o;
    o.x = acc.x * ml + oh.x * tm;
    o.y = acc.y * ml + oh.y * tm;
    *(float2*)(d_h2 + (size_t)g * NN * CC + (size_t)node * CC + 2 * lane) = o;
}

// ---------------- launch ----------------
extern "C" void kernel_launch(void* const* d_in, const int* in_sizes, int n_in,
                              void* d_out, int out_size) {
    const float* features0  = (const float*)d_in[0];
    const float* label_init = (const float*)d_in[1];
    const float* labels_oh  = (const float*)d_in[2];
    const float* train_mask = (const float*)d_in[3];
    const int*   src        = (const int*)d_in[4];
    const int*   dst        = (const int*)d_in[5];
    const float* e_edges    = (const float*)d_in[6];
    const float* attention  = (const float*)d_in[7];
    const float* alpha      = (const float*)d_in[8];
    const float* W1         = (const float*)d_in[9];
    const float* b1         = (const float*)d_in[10];
    const float* W2         = (const float*)d_in[11];
    const float* b2         = (const float*)d_in[12];

    float* out = (float*)d_out;
    float* lp;
    float* ns;
    if (out_size >= 3 * NN * CC) {
        lp = out + (size_t)NN * CC;
        ns = out + 2 * (size_t)NN * CC;
    } else {
        void* p;
        cudaGetSymbolAddress(&p, d_lp_fb); lp = (float*)p;
        cudaGetSymbolAddress(&p, d_ns_fb); ns = (float*)p;
    }

    float* h2base; { void* p; cudaGetSymbolAddress(&p, d_h2); h2base = (float*)p; }
    __nv_bfloat16 *Ahi, *Alo, *W1Thi, *W1Tlo, *HMhi, *HMlo, *W2Thi, *W2Tlo;
    { void* p; cudaGetSymbolAddress(&p, d_Ahi);   Ahi   = (__nv_bfloat16*)p; }
    { void* p; cudaGetSymbolAddress(&p, d_Alo);   Alo   = (__nv_bfloat16*)p; }
    { void* p; cudaGetSymbolAddress(&p, d_W1Thi); W1Thi = (__nv_bfloat16*)p; }
    { void* p; cudaGetSymbolAddress(&p, d_W1Tlo); W1Tlo = (__nv_bfloat16*)p; }
    { void* p; cudaGetSymbolAddress(&p, d_HMhi);  HMhi  = (__nv_bfloat16*)p; }
    { void* p; cudaGetSymbolAddress(&p, d_HMlo);  HMlo  = (__nv_bfloat16*)p; }
    { void* p; cudaGetSymbolAddress(&p, d_W2Thi); W2Thi = (__nv_bfloat16*)p; }
    { void* p; cudaGetSymbolAddress(&p, d_W2Tlo); W2Tlo = (__nv_bfloat16*)p; }

    // GEMM1: BM=64, BN=128 -> (4*64*40 + 4*128*40)*2 = 61440
    // GEMM2: BM=128, BN=64 -> (4*128*40 + 4*64*40)*2 = 61440
    constexpr int SMEM1 = (4 * 64 * 40 + 4 * 128 * 40) * 2;
    constexpr int SMEM2 = (4 * 128 * 40 + 4 * 64 * 40) * 2;
    cudaFuncSetAttribute((const void*)hmma_gemm_kernel<64, 128, 0>,
                         cudaFuncAttributeMaxDynamicSharedMemorySize, SMEM1);
    cudaFuncSetAttribute((const void*)hmma_gemm_kernel<128, 64, 1>,
                         cudaFuncAttributeMaxDynamicSharedMemorySize, SMEM2);

    // ---- fork-join: branch B (MLP path: GEMM1 + ns GEMM) on side stream ----
    cudaStream_t sB = 0;
    cudaEvent_t evFork = 0, evJoin = 0;
    bool forked = (cudaStreamCreateWithFlags(&sB, cudaStreamNonBlocking) == cudaSuccess) &&
                  (cudaEventCreateWithFlags(&evFork, cudaEventDisableTiming) == cudaSuccess) &&
                  (cudaEventCreateWithFlags(&evJoin, cudaEventDisableTiming) == cudaSuccess);
    cudaStream_t b = forked ? sB : (cudaStream_t)0;

    if (forked) {
        cudaEventRecord(evFork, 0);          // fork point on capture-origin stream
        cudaStreamWaitEvent(sB, evFork, 0);  // sB joins the capture graph
    }

    // ---- branch B: conversions + GEMM1 + ns GEMM (all tensor-pipe work) ----
    convA_kernel<<<(NN * DD / 4 + 255) / 256, 256, 0, b>>>(features0, Ahi, Alo, NN * DD / 4);
    convWT_kernel<<<(DD * HH + 255) / 256, 256, 0, b>>>(W1, W1Thi, W1Tlo, DD, HH);
    convWT_kernel<<<(HH * CC + 255) / 256, 256, 0, b>>>(W2, W2Thi, W2Tlo, HH, CC);
    {
        dim3 grid((NN + 63) / 64, HH / 128);
        hmma_gemm_kernel<64, 128, 0><<<grid, 256, SMEM1, b>>>(
            Ahi, Alo, W1Thi, W1Tlo, NN, b1, HMhi, HMlo, nullptr);
    }
    {
        dim3 grid((NN + 127) / 128, 1);
        hmma_gemm_kernel<128, 64, 1><<<grid, 256, SMEM2, b>>>(
            HMhi, HMlo, W2Thi, W2Tlo, NN, b2, nullptr, nullptr, ns);
    }

    // ---- branch A (origin stream): CSR build + label propagation ----
    convL16_kernel<<<(NN * CC / 2 + 255) / 256, 256>>>(label_init, NN * CC / 2);
    zero_deg_kernel<<<(GG * NN + 255) / 256, 256>>>();
    hist_kernel<<<(GG * EE + 255) / 256, 256>>>(dst);
    { dim3 g1(NBLK, GG); scan1_kernel<<<g1, 1024>>>(); }
    scan2_kernel<<<1, 32>>>();
    scan3_kernel<<<(GG * NN + 255) / 256, 256>>>();
    scatter_kernel<<<(GG * EE + 255) / 256, 256>>>(src, dst, e_edges);

    int pblocks = (GG * NN * 32 + 255) / 256;
    prop_l0_kernel<<<pblocks, 256>>>(train_mask, labels_oh);
    prop_l1_kernel<<<pblocks, 256>>>(train_mask, labels_oh);

    // ---- join: combine needs ns (branch B) and h2 (branch A) ----
    if (forked) {
        cudaEventRecord(evJoin, sB);
        cudaStreamWaitEvent(0, evJoin, 0);
    }
    combine_kernel<<<(NN * CC / 4 + 255) / 256, 256>>>(
        attention, alpha,
        h2base, h2base + (size_t)NN * CC, h2base + 2 * (size_t)NN * CC,
        ns, lp, out);

    if (forked) {
        cudaEventDestroy(evFork);
        cudaEventDestroy(evJoin);
        cudaStreamDestroy(sB);
    } else {
        if (evFork) cudaEventDestroy(evFork);
        if (evJoin) cudaEventDestroy(evJoin);
        if (sB) cudaStreamDestroy(sB);
    }
}